// round 8
// baseline (speedup 1.0000x reference)
#include <cuda_runtime.h>
#include <cstdint>

#define THREADS  512
#define TILE     128
#define K1       160
#define N1       128
#define K2       128
#define N2       64
#define NODE_DIM 64
#define EDGE_DIM 32

// byte strides, padded for conflict-free ldmatrix (odd multiples of 16)
#define ASTB   176   // A + W1T row stride (k=160 int8 + pad)
#define HSTB   144   // h + W2T row stride (k=128 int8 + pad)
#define PST    72    // partial row stride in words

// smem offsets (bytes)
#define OFF_W1H  0
#define OFF_W1L  22528
#define OFF_W2H  45056
#define OFF_W2L  54272
#define OFF_AH   63488
#define OFF_AL   86016
#define OFF_HH   108544
#define OFF_HL   126976
#define OFF_P    145408
#define OFF_B1   182272
#define OFF_B2   182784
#define OFF_IS64 183040
#define SMEM_TOTAL 183104

#define SA   2048.0f
#define SW   32768.0f
#define SH   2048.0f
#define INV26 (1.0f/67108864.0f)

__device__ __forceinline__ uint32_t s2u(const void* p){
    uint32_t a;
    asm("{ .reg .u64 t; cvta.to.shared.u64 t, %1; cvt.u32.u64 %0, t; }" : "=r"(a) : "l"(p));
    return a;
}
__device__ __forceinline__ void ldsm4(uint32_t& r0, uint32_t& r1, uint32_t& r2, uint32_t& r3,
                                      uint32_t addr){
    asm volatile("ldmatrix.sync.aligned.m8n8.x4.shared.b16 {%0,%1,%2,%3}, [%4];"
                 : "=r"(r0), "=r"(r1), "=r"(r2), "=r"(r3) : "r"(addr));
}
__device__ __forceinline__ void imma(int* c,
                                     uint32_t a0, uint32_t a1, uint32_t a2, uint32_t a3,
                                     uint32_t b0, uint32_t b1){
    asm volatile("mma.sync.aligned.m16n8k32.row.col.s32.s8.s8.s32 "
                 "{%0,%1,%2,%3}, {%4,%5,%6,%7}, {%8,%9}, {%0,%1,%2,%3};"
                 : "+r"(c[0]), "+r"(c[1]), "+r"(c[2]), "+r"(c[3])
                 : "r"(a0), "r"(a1), "r"(a2), "r"(a3), "r"(b0), "r"(b1));
}
// round-to-nearest 15-bit fixed point quantize (|v*S| < 2^22 required)
__device__ __forceinline__ int qz(float v, float S){
    float m = fmaf(v, S, 12582912.0f);
    int i = __float_as_int(m) - 0x4B400000;
    return min(16319, max(-16319, i));
}
__device__ __forceinline__ void qsplit(float v, float S, int& hi, int& lo){
    int i = qz(v, S);
    hi = (i + 64) >> 7;         // [-127,127]
    lo = i - (hi << 7);         // [-64,63]
}
__device__ __forceinline__ uint32_t pack4(int a, int b, int c, int d){
    return (uint32_t)(a & 255) | ((uint32_t)(b & 255) << 8) |
           ((uint32_t)(c & 255) << 16) | ((uint32_t)(d & 255) << 24);
}

__global__ __launch_bounds__(THREADS, 1)
void edge_mlp_imma(const float* __restrict__ x,
                   const float* __restrict__ edge_attr,
                   const float* __restrict__ W1,
                   const float* __restrict__ b1,
                   const float* __restrict__ W2,
                   const float* __restrict__ b2,
                   const void*  __restrict__ edge_index,
                   float* __restrict__ out,
                   int n_edges, int n_nodes)
{
    extern __shared__ __align__(1024) char sm[];
    const uint32_t smb = s2u(sm);
    const int tid = threadIdx.x;
    const int wid = tid >> 5;
    const int lid = tid & 31;
    const int wrow = wid >> 1;     // 0..7: 16-edge row group
    const int wcol = wid & 1;      // 0..1: 64-col k/hidden half

    float* b1s = (float*)(sm + OFF_B1);
    float* b2s = (float*)(sm + OFF_B2);

    if (tid == 0) {
        const long long* e64 = (const long long*)edge_index;
        int ok = 1;
        #pragma unroll 1
        for (int i = 0; i < 32; i++) {
            long long v = e64[i];
            if (v < 0 || v >= (long long)n_nodes) ok = 0;
        }
        *(int*)(sm + OFF_IS64) = ok;
    }

    // ---- weights: transpose to [n][k], int8 radix-128 split ----
    for (int i = tid; i < K1 * N1; i += THREADS) {
        int k = i >> 7, n = i & 127;
        int hi, lo; qsplit(W1[i], SW, hi, lo);
        int off = n * ASTB + k;
        *(signed char*)(sm + OFF_W1H + off) = (signed char)hi;
        *(signed char*)(sm + OFF_W1L + off) = (signed char)lo;
    }
    for (int i = tid; i < K2 * N2; i += THREADS) {
        int k = i >> 6, n = i & 63;
        int hi, lo; qsplit(W2[i], SW, hi, lo);
        int off = n * HSTB + k;
        *(signed char*)(sm + OFF_W2H + off) = (signed char)hi;
        *(signed char*)(sm + OFF_W2L + off) = (signed char)lo;
    }
    if (tid < N1) b1s[tid] = b1[tid];
    if (tid < N2) b2s[tid] = b2[tid];
    __syncthreads();

    const int is64 = *(int*)(sm + OFF_IS64);
    const long long* idx64 = (const long long*)edge_index;
    const int*       idx32 = (const int*)edge_index;

    // gather: 4 threads per row, 10 float4 each
    const int grow = tid >> 2;
    const int gq   = tid & 3;

    // ldmatrix lane addressing
    const int lmrow = lid & 15;
    const int lmk16 = (lid >> 4) << 4;               // byte offset 0/16
    const int bn    = ((lid >> 4) << 3) + (lid & 7); // B row within 16
    const int bkB   = ((lid >> 3) & 1) << 4;         // byte offset 0/16

    const uint32_t aAH = smb + OFF_AH + (uint32_t)((wrow * 16 + lmrow) * ASTB + lmk16);
    const uint32_t aAL = smb + OFF_AL + (uint32_t)((wrow * 16 + lmrow) * ASTB + lmk16);
    const uint32_t aW1H = smb + OFF_W1H + (uint32_t)((wcol * 64 + bn) * ASTB + bkB);
    const uint32_t aW1L = smb + OFF_W1L + (uint32_t)((wcol * 64 + bn) * ASTB + bkB);
    const uint32_t aHH = smb + OFF_HH + (uint32_t)((wrow * 16 + lmrow) * HSTB + wcol * 64 + lmk16);
    const uint32_t aHL = smb + OFF_HL + (uint32_t)((wrow * 16 + lmrow) * HSTB + wcol * 64 + lmk16);
    const uint32_t aW2H = smb + OFF_W2H + (uint32_t)(bn * HSTB + wcol * 64 + bkB);
    const uint32_t aW2L = smb + OFF_W2L + (uint32_t)(bn * HSTB + wcol * 64 + bkB);

    const int q2 = (lid & 3) << 1;
    const int prow = lid >> 2;
    int* Ppart = (int*)(sm + OFF_P) + wrow * (16 * PST);

    const int n_tiles = (n_edges + TILE - 1) / TILE;
    for (int tile = blockIdx.x; tile < n_tiles; tile += gridDim.x) {
        const int e_base = tile * TILE;

        // ================= gather -> A hi/lo int8 =================
        {
            const int ge = e_base + grow;
            const float* xs = x;
            const float* xt = x;
            const float* ea = edge_attr;
            bool valid = (ge < n_edges);
            if (valid) {
                long long s, t;
                if (is64) { s = idx64[ge]; t = idx64[ge + n_edges]; }
                else      { s = idx32[ge]; t = idx32[ge + n_edges]; }
                xs = x + s * NODE_DIM;
                xt = x + t * NODE_DIM;
                ea = edge_attr + (long long)ge * EDGE_DIM;
            }
            char* rowH = sm + OFF_AH + grow * ASTB;
            char* rowL = sm + OFF_AL + grow * ASTB;
            #pragma unroll
            for (int j = 0; j < 10; j++) {
                const int col = (gq * 10 + j) * 4;
                float4 v = make_float4(0.f, 0.f, 0.f, 0.f);
                if (valid) {
                    if (col < 64)       v = *(const float4*)(xs + col);
                    else if (col < 128) v = *(const float4*)(xt + (col - 64));
                    else                v = *(const float4*)(ea + (col - 128));
                }
                int h0,l0,h1,l1,h2,l2,h3,l3;
                qsplit(v.x, SA, h0, l0);
                qsplit(v.y, SA, h1, l1);
                qsplit(v.z, SA, h2, l2);
                qsplit(v.w, SA, h3, l3);
                *(uint32_t*)(rowH + col) = pack4(h0, h1, h2, h3);
                *(uint32_t*)(rowL + col) = pack4(l0, l1, l2, l3);
            }
        }
        __syncthreads();

        // ================= GEMM1 + epilogue1, two 32-col half-passes =================
        #pragma unroll
        for (int hf = 0; hf < 2; hf++) {
            int C11[4][4], Cm[4][4], C00[4][4];
            #pragma unroll
            for (int i = 0; i < 4; i++)
                #pragma unroll
                for (int j = 0; j < 4; j++) { C11[i][j] = 0; Cm[i][j] = 0; C00[i][j] = 0; }

            #pragma unroll
            for (int c = 0; c < 5; c++) {
                uint32_t ah0,ah1,ah2,ah3, al0,al1,al2,al3;
                ldsm4(ah0, ah1, ah2, ah3, aAH + c * 32);
                ldsm4(al0, al1, al2, al3, aAL + c * 32);
                #pragma unroll
                for (int nt2 = 0; nt2 < 2; nt2++) {
                    uint32_t bh0,bh1,bh2,bh3, bl0,bl1,bl2,bl3;
                    const uint32_t boff = (uint32_t)((hf * 2 + nt2) * 16 * ASTB) + c * 32;
                    ldsm4(bh0, bh1, bh2, bh3, aW1H + boff);
                    ldsm4(bl0, bl1, bl2, bl3, aW1L + boff);
                    imma(C11[2*nt2],   ah0,ah1,ah2,ah3, bh0,bh1);
                    imma(Cm [2*nt2],   al0,al1,al2,al3, bh0,bh1);
                    imma(Cm [2*nt2],   ah0,ah1,ah2,ah3, bl0,bl1);
                    imma(C00[2*nt2],   al0,al1,al2,al3, bl0,bl1);
                    imma(C11[2*nt2+1], ah0,ah1,ah2,ah3, bh2,bh3);
                    imma(Cm [2*nt2+1], al0,al1,al2,al3, bh2,bh3);
                    imma(Cm [2*nt2+1], ah0,ah1,ah2,ah3, bl2,bl3);
                    imma(C00[2*nt2+1], al0,al1,al2,al3, bl2,bl3);
                }
            }

            // epilogue1: exact combine -> bias+relu -> requantize -> h tiles
            #pragma unroll
            for (int mm = 0; mm < 4; mm++) {
                const int nt  = hf * 4 + mm;
                const int cgl = wcol * 64 + nt * 8 + q2;
                const float2 bb = *(const float2*)(b1s + cgl);
                int t0 = (C11[mm][0] << 14) + (Cm[mm][0] << 7) + C00[mm][0];
                int t1 = (C11[mm][1] << 14) + (Cm[mm][1] << 7) + C00[mm][1];
                int t2 = (C11[mm][2] << 14) + (Cm[mm][2] << 7) + C00[mm][2];
                int t3 = (C11[mm][3] << 14) + (Cm[mm][3] << 7) + C00[mm][3];
                float p0 = fmaxf(fmaf((float)t0, INV26, bb.x), 0.f);
                float p1 = fmaxf(fmaf((float)t1, INV26, bb.y), 0.f);
                float p2 = fmaxf(fmaf((float)t2, INV26, bb.x), 0.f);
                float p3 = fmaxf(fmaf((float)t3, INV26, bb.y), 0.f);
                int h0,l0,h1,l1,h2,l2,h3,l3;
                qsplit(p0, SH, h0, l0);
                qsplit(p1, SH, h1, l1);
                qsplit(p2, SH, h2, l2);
                qsplit(p3, SH, h3, l3);
                const int R0 = wrow * 16 + prow;
                *(unsigned short*)(sm + OFF_HH + R0 * HSTB + cgl) =
                    (unsigned short)((h0 & 255) | ((h1 & 255) << 8));
                *(unsigned short*)(sm + OFF_HL + R0 * HSTB + cgl) =
                    (unsigned short)((l0 & 255) | ((l1 & 255) << 8));
                *(unsigned short*)(sm + OFF_HH + (R0 + 8) * HSTB + cgl) =
                    (unsigned short)((h2 & 255) | ((h3 & 255) << 8));
                *(unsigned short*)(sm + OFF_HL + (R0 + 8) * HSTB + cgl) =
                    (unsigned short)((l2 & 255) | ((l3 & 255) << 8));
            }
        }
        __syncwarp();   // h block is written and read only by this warp

        // ================= GEMM2 partial over this warp's 64-k half =================
        int T2[8][4];
        #pragma unroll
        for (int hf = 0; hf < 2; hf++) {
            int C11[4][4], Cm[4][4], C00[4][4];
            #pragma unroll
            for (int i = 0; i < 4; i++)
                #pragma unroll
                for (int j = 0; j < 4; j++) { C11[i][j] = 0; Cm[i][j] = 0; C00[i][j] = 0; }

            #pragma unroll
            for (int c = 0; c < 2; c++) {
                uint32_t ah0,ah1,ah2,ah3, al0,al1,al2,al3;
                ldsm4(ah0, ah1, ah2, ah3, aHH + c * 32);
                ldsm4(al0, al1, al2, al3, aHL + c * 32);
                #pragma unroll
                for (int nt2 = 0; nt2 < 2; nt2++) {
                    uint32_t bh0,bh1,bh2,bh3, bl0,bl1,bl2,bl3;
                    const uint32_t boff = (uint32_t)((hf * 2 + nt2) * 16 * HSTB) + c * 32;
                    ldsm4(bh0, bh1, bh2, bh3, aW2H + boff);
                    ldsm4(bl0, bl1, bl2, bl3, aW2L + boff);
                    imma(C11[2*nt2],   ah0,ah1,ah2,ah3, bh0,bh1);
                    imma(Cm [2*nt2],   al0,al1,al2,al3, bh0,bh1);
                    imma(Cm [2*nt2],   ah0,ah1,ah2,ah3, bl0,bl1);
                    imma(C00[2*nt2],   al0,al1,al2,al3, bl0,bl1);
                    imma(C11[2*nt2+1], ah0,ah1,ah2,ah3, bh2,bh3);
                    imma(Cm [2*nt2+1], al0,al1,al2,al3, bh2,bh3);
                    imma(Cm [2*nt2+1], ah0,ah1,ah2,ah3, bl2,bl3);
                    imma(C00[2*nt2+1], al0,al1,al2,al3, bl2,bl3);
                }
            }
            #pragma unroll
            for (int mm = 0; mm < 4; mm++)
                #pragma unroll
                for (int j = 0; j < 4; j++)
                    T2[hf*4+mm][j] = (C11[mm][j] << 14) + (Cm[mm][j] << 7) + C00[mm][j];
        }

        // odd warps store their k-half partials (exact int)
        if (wcol) {
            #pragma unroll
            for (int nt = 0; nt < 8; nt++) {
                const int c = nt * 8 + q2;
                *(int2*)(Ppart + prow * PST + c)       = make_int2(T2[nt][0], T2[nt][1]);
                *(int2*)(Ppart + (prow + 8) * PST + c) = make_int2(T2[nt][2], T2[nt][3]);
            }
        }
        __syncthreads();

        // even warps reduce, dequantize, add b2, store
        if (!wcol) {
            const int r0 = e_base + wrow * 16 + prow;
            #pragma unroll
            for (int nt = 0; nt < 8; nt++) {
                const int c = nt * 8 + q2;
                const float2 bb = *(const float2*)(b2s + c);
                const int2 p0 = *(const int2*)(Ppart + prow * PST + c);
                const int2 p1 = *(const int2*)(Ppart + (prow + 8) * PST + c);
                if (r0 < n_edges) {
                    float2 o0;
                    o0.x = fmaf((float)(T2[nt][0] + p0.x), INV26, bb.x);
                    o0.y = fmaf((float)(T2[nt][1] + p0.y), INV26, bb.y);
                    *(float2*)(out + (size_t)r0 * N2 + c) = o0;
                }
                if (r0 + 8 < n_edges) {
                    float2 o1;
                    o1.x = fmaf((float)(T2[nt][2] + p1.x), INV26, bb.x);
                    o1.y = fmaf((float)(T2[nt][3] + p1.y), INV26, bb.y);
                    *(float2*)(out + (size_t)(r0 + 8) * N2 + c) = o1;
                }
            }
        }
        // next gather's post-gather barrier protects A; P protected by it too
    }
}

extern "C" void kernel_launch(void* const* d_in, const int* in_sizes, int n_in,
                              void* d_out, int out_size)
{
    const float* x  = (const float*)d_in[0];
    const float* ea = (const float*)d_in[1];
    const float* W1 = (const float*)d_in[2];
    const float* b1 = (const float*)d_in[3];
    const float* W2 = (const float*)d_in[4];
    const float* b2 = (const float*)d_in[5];
    const void*  ei = (const void*)d_in[6];
    float* out = (float*)d_out;

    const int n_nodes = in_sizes[0] / NODE_DIM;
    const int n_edges = in_sizes[1] / EDGE_DIM;
    const int n_tiles = (n_edges + TILE - 1) / TILE;
    int grid = n_tiles < 148 ? n_tiles : 148;

    cudaFuncSetAttribute(edge_mlp_imma,
                         cudaFuncAttributeMaxDynamicSharedMemorySize, SMEM_TOTAL);
    edge_mlp_imma<<<grid, THREADS, SMEM_TOTAL>>>(
        x, ea, W1, b1, W2, b2, ei, out, n_edges, n_nodes);
}